// round 10
// baseline (speedup 1.0000x reference)
#include <cuda_runtime.h>
#include <cstdint>

#define Hh 200
#define Ww 196
#define Cc 256
#define NCAMS 6
#define SSZ 400
#define NCELLS (SSZ*SSZ)
#define NPTS (Hh*Ww)     // 39200
#define HQ (Hh/4)        // 50
#define NSEG 4           // channel groups
#define CPG (Cc/NSEG)    // 64 channels per group
#define NTHREADS (NCAMS*Ww*NSEG*HQ)   // 235200 -> 919 CTAs of 256
#define NQ (NCELLS/4)
#define NPQ (Ww*HQ)      // 9800 cell-kernel threads

// Zero-initialized at module load; final_kernel resets sum/cnt each launch so
// every launch / graph replay sees zeroed scratch. g_cell is fully rewritten
// by cell_kernel each launch (deterministic).
__device__ float g_sum[NCELLS];
__device__ float g_cnt[NCELLS];
__device__ int   g_cell[NCAMS * NPTS];   // [cam][w*Hh + h] = cell or -1

// Precompute per (cam, point): projected cell index (mask+bounds folded in),
// stored TRANSPOSED (h innermost) for coalesced int4 reads by the main kernel,
// AND the per-cell counts (pure geometry -> done here, off the hot kernel).
// One thread per (w, h-quad): 12 independent scattered loads (lc x8, mask x4)
// -> deep MLP; int4 stores coalesced. Warp 0 of each block fingerprints the
// mask dtype (mask ~90% true) over the first 384 bytes:
//   int32 0/1 : low byte of words sometimes set, upper 3 bytes never
//   f32 0/1.0 : low byte never, upper bytes sometimes (0x3f800000)
//   u8 bool   : both populated
__global__ void __launch_bounds__(256) cell_kernel(
    const float* __restrict__ cam, const float* __restrict__ lc,
    const void* __restrict__ mask)
{
    __shared__ int s_mode;
    if (threadIdx.x < 32) {
        const unsigned* mw = (const unsigned*)mask;
        unsigned lo = 0, hi = 0;
        #pragma unroll
        for (int k = 0; k < 3; ++k) {
            unsigned v = mw[threadIdx.x + 32 * k];
            lo |= (v & 0xFFu);
            hi |= (v & 0xFFFFFF00u);
        }
        unsigned any_lo = __ballot_sync(0xFFFFFFFF, lo != 0);
        unsigned any_hi = __ballot_sync(0xFFFFFFFF, hi != 0);
        if (threadIdx.x == 0) {
            int mode;
            if (any_lo && any_hi) mode = 1;   // u8 bool
            else if (any_lo)      mode = 0;   // int32
            else                  mode = 2;   // float32
            s_mode = mode;
        }
    }
    __syncthreads();

    int tid = blockIdx.x * blockDim.x + threadIdx.x;
    if (tid >= NPQ) return;
    int mode = s_mode;
    int hq = tid % HQ;
    int w  = tid / HQ;
    int h0 = hq * 4;

    float xs[4], ys[4];
    bool  mv[4];
    #pragma unroll
    for (int k = 0; k < 4; ++k) {
        int n = (h0 + k) * Ww + w;       // ravel order of (H, W)
        xs[k] = __ldg(lc + n);           // row 0 of logits_coordinates
        ys[k] = __ldg(lc + NPTS + n);    // row 1
        if (mode == 1)      mv[k] = ((const unsigned char*)mask)[n] != 0;
        else if (mode == 0) mv[k] = ((const int*)mask)[n] != 0;
        else                mv[k] = ((const float*)mask)[n] != 0.f;
    }

    #pragma unroll
    for (int c = 0; c < NCAMS; ++c) {
        const float* M = cam + c * 16;
        float m00 = __ldg(M + 0), m01 = __ldg(M + 1), m03 = __ldg(M + 3);
        float m10 = __ldg(M + 4), m11 = __ldg(M + 5), m13 = __ldg(M + 7);
        int4 cells;
        int* cl = (int*)&cells;
        #pragma unroll
        for (int k = 0; k < 4; ++k) {
            float c0 = fmaf(m00, xs[k], fmaf(m01, ys[k], m03));
            float c1 = fmaf(m10, xs[k], fmaf(m11, ys[k], m13));
            // (coord+100)/0.5 == (coord+100)*2 exactly; jnp.round = half-even
            int i0 = (int)rintf((c0 + 100.0f) * 2.0f);
            int i1 = (int)rintf((c1 + 100.0f) * 2.0f);
            int cell = (mv[k] && i0 >= 0 && i0 < SSZ && i1 >= 0 && i1 < SSZ)
                         ? (i0 * SSZ + i1) : -1;
            cl[k] = cell;
            if (cell >= 0) atomicAdd(&g_cnt[cell], 1.0f);
        }
        *(int4*)(g_cell + c * NPTS + w * Hh + h0) = cells;   // coalesced
    }
}

// One thread per (cam, w, chan-group, h-quad). Streams td_feats exactly once
// (coalesced float4 over innermost h), partial-dots 64 channels against s_w.
// Launched with ProgrammaticStreamSerialization: overlaps cell_kernel; the
// griddepcontrol.wait (acquire) before reading g_cell is the only sync point.
__global__ void __launch_bounds__(256) fused_dot_scatter_kernel(
    const float* __restrict__ td, const float* __restrict__ wcls)
{
    __shared__ float s_w[Cc];
    for (int i = threadIdx.x; i < Cc; i += blockDim.x) s_w[i] = wcls[i];
    __syncthreads();

    int tid = blockIdx.x * blockDim.x + threadIdx.x;
    if (tid >= NTHREADS) {
        asm volatile("griddepcontrol.wait;" ::: "memory");
        return;
    }
    // hq innermost for coalescing, then chan-group, then w, then cam
    int hq  = tid % HQ;
    int t2  = tid / HQ;
    int seg = t2 % NSEG;
    int t3  = t2 / NSEG;
    int w   = t3 % Ww;
    int c   = t3 / Ww;
    int h0  = hq * 4;
    int ch0 = seg * CPG;

    // td flat index: ((c*C + ch)*W + w)*H + h ; h innermost, 16B aligned (H%4==0)
    const float4* __restrict__ base =
        (const float4*)(td + ((size_t)(c * Cc + ch0) * Ww + w) * Hh + h0);
    const int ch_stride4 = (Ww * Hh) / 4;   // 9800 float4 between channels

    float acc0 = 0.f, acc1 = 0.f, acc2 = 0.f, acc3 = 0.f;
    #pragma unroll 8
    for (int ch = 0; ch < CPG; ++ch) {
        float4 v = __ldg(base + ch * ch_stride4);
        float wv = s_w[ch0 + ch];
        acc0 = fmaf(v.x, wv, acc0);
        acc1 = fmaf(v.y, wv, acc1);
        acc2 = fmaf(v.z, wv, acc2);
        acc3 = fmaf(v.w, wv, acc3);
    }

    // Wait for cell_kernel (PDL edge) before touching its outputs.
    asm volatile("griddepcontrol.wait;" ::: "memory");

    int4 cells = __ldg((const int4*)(g_cell + c * NPTS + w * Hh + h0));
    float accs[4] = {acc0, acc1, acc2, acc3};
    int   cls[4]  = {cells.x, cells.y, cells.z, cells.w};
    #pragma unroll
    for (int k = 0; k < 4; ++k) {
        if (cls[k] >= 0)
            atomicAdd(&g_sum[cls[k]], accs[k]);   // partial dot; linear so OK
    }
}

// Consumes the accumulators AND resets them to zero for the next launch.
// Two independent pairs per thread for load ILP.
__global__ void __launch_bounds__(256) final_kernel(float* __restrict__ out,
                                                    const float* __restrict__ bcls) {
    int i = blockIdx.x * blockDim.x + threadIdx.x;
    if (i >= NQ / 2) return;
    int j = i + NQ / 2;
    float b = __ldg(bcls);
    float4 s0 = ((const float4*)g_sum)[i];
    float4 n0 = ((const float4*)g_cnt)[i];
    float4 s1 = ((const float4*)g_sum)[j];
    float4 n1 = ((const float4*)g_cnt)[j];
    float4 o0, o1;
    o0.x = s0.x / fmaxf(n0.x, 1.0f) + b;   // cnt==0 -> sum==0 -> b (matches ref)
    o0.y = s0.y / fmaxf(n0.y, 1.0f) + b;
    o0.z = s0.z / fmaxf(n0.z, 1.0f) + b;
    o0.w = s0.w / fmaxf(n0.w, 1.0f) + b;
    o1.x = s1.x / fmaxf(n1.x, 1.0f) + b;
    o1.y = s1.y / fmaxf(n1.y, 1.0f) + b;
    o1.z = s1.z / fmaxf(n1.z, 1.0f) + b;
    o1.w = s1.w / fmaxf(n1.w, 1.0f) + b;
    ((float4*)out)[i] = o0;
    ((float4*)out)[j] = o1;
    float4 z = make_float4(0.f, 0.f, 0.f, 0.f);
    ((float4*)g_sum)[i] = z;
    ((float4*)g_cnt)[i] = z;
    ((float4*)g_sum)[j] = z;
    ((float4*)g_cnt)[j] = z;
}

extern "C" void kernel_launch(void* const* d_in, const int* in_sizes, int n_in,
                              void* d_out, int out_size) {
    const float* td   = (const float*)d_in[0];  // (1,6,256,196,200) f32
    const float* cam  = (const float*)d_in[1];  // (1,6,4,4) f32
    const float* lc   = (const float*)d_in[2];  // (4,39200) f32
    const void*  mask = (const void*) d_in[3];  // (200,196) bool-ish
    const float* wcls = (const float*)d_in[4];  // (256,) f32
    const float* bcls = (const float*)d_in[5];  // () f32
    float* out = (float*)d_out;                 // (1,1,400,400) f32

    cell_kernel<<<(NPQ + 255) / 256, 256>>>(cam, lc, mask);

    // Main kernel with Programmatic Dependent Launch: starts while cell_kernel
    // runs; griddepcontrol.wait inside orders the g_cell reads.
    {
        cudaLaunchConfig_t cfg = {};
        cfg.gridDim  = dim3((NTHREADS + 255) / 256);
        cfg.blockDim = dim3(256);
        cfg.dynamicSmemBytes = 0;
        cfg.stream = 0;
        cudaLaunchAttribute attr[1];
        attr[0].id = cudaLaunchAttributeProgrammaticStreamSerialization;
        attr[0].val.programmaticStreamSerializationAllowed = 1;
        cfg.attrs = attr;
        cfg.numAttrs = 1;
        cudaLaunchKernelEx(&cfg, fused_dot_scatter_kernel, td, wcls);
    }

    final_kernel<<<(NQ / 2 + 255) / 256, 256>>>(out, bcls);
}

// round 11
// speedup vs baseline: 1.0164x; 1.0164x over previous
#include <cuda_runtime.h>
#include <cstdint>

#define Hh 200
#define Ww 196
#define Cc 256
#define NCAMS 6
#define SSZ 400
#define NCELLS (SSZ*SSZ)
#define NPTS (Hh*Ww)     // 39200
#define HQ (Hh/4)        // 50
#define NSEG 4           // channel groups
#define CPG (Cc/NSEG)    // 64 channels per group
#define NTHREADS (NCAMS*Ww*NSEG*HQ)   // 235200 -> 919 CTAs of 256
#define NQ (NCELLS/4)
#define NPQ (Ww*HQ)                   // 9800 h-quads
#define NCPT (NCAMS*NPQ)              // 58800 cell tasks (one per cam x h-quad)
#define NBLK_CELL ((NCPT + 255) / 256)  // 230 producer blocks

// Zero-initialized at module load; final_kernel resets sum/cnt/g_done each
// launch so every launch / graph replay sees zeroed scratch. g_cell is fully
// rewritten by the prologue each launch (deterministic).
__device__ float    g_sum[NCELLS];
__device__ float    g_cnt[NCELLS];
__device__ int      g_cell[NCAMS * NPTS];  // [cam][w*Hh + h] = cell or -1
__device__ unsigned g_done;                // producer-block arrival counter

// Single hot kernel:
//  Prologue (blocks 0..229): compute the projected cell table (mask+bounds
//    folded in, stored TRANSPOSED for coalesced int4 reads) AND the per-cell
//    counts; arrive on g_done. ~0.5us of work, runs concurrently with every
//    other block's streaming.
//  Body (all blocks): stream td_feats once (coalesced float4 over innermost
//    h), partial-dot 64 channels vs s_w.
//  Epilogue: wait g_done==230 (long since satisfied), one coalesced int4
//    cell load, <=4 predicated sum atomics.
__global__ void fused_dot_scatter_kernel(
    const float* __restrict__ td, const float* __restrict__ cam,
    const float* __restrict__ lc, const void*  __restrict__ mask,
    const float* __restrict__ wcls)
{
    __shared__ float s_w[Cc];
    __shared__ int   s_mode;

    const bool cellblock = blockIdx.x < NBLK_CELL;

    // Mask-dtype fingerprint (mask ~90% true) over first 384 bytes:
    //   int32 0/1 : low byte of words sometimes set, upper 3 bytes never
    //   f32 0/1.0 : low byte never, upper bytes sometimes (0x3f800000)
    //   u8 bool   : both populated
    if (cellblock && threadIdx.x < 32) {
        const unsigned* mw = (const unsigned*)mask;
        unsigned lo = 0, hi = 0;
        #pragma unroll
        for (int k = 0; k < 3; ++k) {
            unsigned v = mw[threadIdx.x + 32 * k];
            lo |= (v & 0xFFu);
            hi |= (v & 0xFFFFFF00u);
        }
        unsigned any_lo = __ballot_sync(0xFFFFFFFF, lo != 0);
        unsigned any_hi = __ballot_sync(0xFFFFFFFF, hi != 0);
        if (threadIdx.x == 0) {
            int mode;
            if (any_lo && any_hi) mode = 1;   // u8 bool
            else if (any_lo)      mode = 0;   // int32
            else                  mode = 2;   // float32
            s_mode = mode;
        }
    }
    for (int i = threadIdx.x; i < Cc; i += blockDim.x) s_w[i] = wcls[i];
    __syncthreads();

    // ---- Prologue: cell table + counts (blocks 0..229) ----
    if (cellblock) {
        int ct = blockIdx.x * blockDim.x + threadIdx.x;
        if (ct < NCPT) {
            int mode = s_mode;
            int hq = ct % HQ;
            int t2 = ct / HQ;
            int w  = t2 % Ww;
            int c  = t2 / Ww;
            int h0 = hq * 4;

            const float* M = cam + c * 16;
            float m00 = __ldg(M + 0), m01 = __ldg(M + 1), m03 = __ldg(M + 3);
            float m10 = __ldg(M + 4), m11 = __ldg(M + 5), m13 = __ldg(M + 7);

            int4 cells;
            int* cl = (int*)&cells;
            #pragma unroll
            for (int k = 0; k < 4; ++k) {
                int n = (h0 + k) * Ww + w;       // ravel order of (H, W)
                float x = __ldg(lc + n);         // row 0 of logits_coordinates
                float y = __ldg(lc + NPTS + n);  // row 1
                bool mv;
                if (mode == 1)      mv = ((const unsigned char*)mask)[n] != 0;
                else if (mode == 0) mv = ((const int*)mask)[n] != 0;
                else                mv = ((const float*)mask)[n] != 0.f;

                float c0 = fmaf(m00, x, fmaf(m01, y, m03));
                float c1 = fmaf(m10, x, fmaf(m11, y, m13));
                // (coord+100)/0.5 == (coord+100)*2 exactly; jnp.round = half-even
                int i0 = (int)rintf((c0 + 100.0f) * 2.0f);
                int i1 = (int)rintf((c1 + 100.0f) * 2.0f);
                int cell = (mv && i0 >= 0 && i0 < SSZ && i1 >= 0 && i1 < SSZ)
                             ? (i0 * SSZ + i1) : -1;
                cl[k] = cell;
                if (cell >= 0) atomicAdd(&g_cnt[cell], 1.0f);  // counts: geometry only
            }
            *(int4*)(g_cell + c * NPTS + w * Hh + h0) = cells; // coalesced
        }
        __syncthreads();
        if (threadIdx.x == 0) {
            __threadfence();                     // publish table + counts
            atomicAdd(&g_done, 1u);
        }
    }

    // ---- Body: stream + partial dot ----
    int tid = blockIdx.x * blockDim.x + threadIdx.x;
    int hq = 0, seg = 0, w = 0, c = 0, h0 = 0;
    float acc0 = 0.f, acc1 = 0.f, acc2 = 0.f, acc3 = 0.f;
    const bool work = tid < NTHREADS;
    if (work) {
        // hq innermost for coalescing, then chan-group, then w, then cam
        hq  = tid % HQ;
        int t2 = tid / HQ;
        seg = t2 % NSEG;
        int t3 = t2 / NSEG;
        w   = t3 % Ww;
        c   = t3 / Ww;
        h0  = hq * 4;
        int ch0 = seg * CPG;

        // td: ((c*C + ch)*W + w)*H + h ; h innermost, 16B aligned (H%4==0)
        const float4* __restrict__ base =
            (const float4*)(td + ((size_t)(c * Cc + ch0) * Ww + w) * Hh + h0);
        const int ch_stride4 = (Ww * Hh) / 4;   // 9800 float4 between channels

        #pragma unroll 8
        for (int ch = 0; ch < CPG; ++ch) {
            float4 v = __ldg(base + ch * ch_stride4);
            float wv = s_w[ch0 + ch];
            acc0 = fmaf(v.x, wv, acc0);
            acc1 = fmaf(v.y, wv, acc1);
            acc2 = fmaf(v.z, wv, acc2);
            acc3 = fmaf(v.w, wv, acc3);
        }
    }

    // ---- Wait for the cell table (satisfied ~35us ago in steady state) ----
    if (threadIdx.x == 0) {
        while (*((volatile unsigned*)&g_done) < NBLK_CELL) { }
    }
    __syncthreads();
    __threadfence();   // acquire: table + counts visible

    if (work) {
        int4 cells = __ldg((const int4*)(g_cell + c * NPTS + w * Hh + h0));
        float accs[4] = {acc0, acc1, acc2, acc3};
        int   cls[4]  = {cells.x, cells.y, cells.z, cells.w};
        #pragma unroll
        for (int k = 0; k < 4; ++k) {
            if (cls[k] >= 0)
                atomicAdd(&g_sum[cls[k]], accs[k]);   // partial dot; linear so OK
        }
    }
}

// Consumes the accumulators AND resets all scratch (sum, cnt, g_done) for the
// next launch. Two independent pairs per thread for load ILP.
__global__ void __launch_bounds__(256) final_kernel(float* __restrict__ out,
                                                    const float* __restrict__ bcls) {
    int i = blockIdx.x * blockDim.x + threadIdx.x;
    if (i == 0) g_done = 0;
    if (i >= NQ / 2) return;
    int j = i + NQ / 2;
    float b = __ldg(bcls);
    float4 s0 = ((const float4*)g_sum)[i];
    float4 n0 = ((const float4*)g_cnt)[i];
    float4 s1 = ((const float4*)g_sum)[j];
    float4 n1 = ((const float4*)g_cnt)[j];
    float4 o0, o1;
    o0.x = s0.x / fmaxf(n0.x, 1.0f) + b;   // cnt==0 -> sum==0 -> b (matches ref)
    o0.y = s0.y / fmaxf(n0.y, 1.0f) + b;
    o0.z = s0.z / fmaxf(n0.z, 1.0f) + b;
    o0.w = s0.w / fmaxf(n0.w, 1.0f) + b;
    o1.x = s1.x / fmaxf(n1.x, 1.0f) + b;
    o1.y = s1.y / fmaxf(n1.y, 1.0f) + b;
    o1.z = s1.z / fmaxf(n1.z, 1.0f) + b;
    o1.w = s1.w / fmaxf(n1.w, 1.0f) + b;
    ((float4*)out)[i] = o0;
    ((float4*)out)[j] = o1;
    float4 z = make_float4(0.f, 0.f, 0.f, 0.f);
    ((float4*)g_sum)[i] = z;
    ((float4*)g_cnt)[i] = z;
    ((float4*)g_sum)[j] = z;
    ((float4*)g_cnt)[j] = z;
}

extern "C" void kernel_launch(void* const* d_in, const int* in_sizes, int n_in,
                              void* d_out, int out_size) {
    const float* td   = (const float*)d_in[0];  // (1,6,256,196,200) f32
    const float* cam  = (const float*)d_in[1];  // (1,6,4,4) f32
    const float* lc   = (const float*)d_in[2];  // (4,39200) f32
    const void*  mask = (const void*) d_in[3];  // (200,196) bool-ish
    const float* wcls = (const float*)d_in[4];  // (256,) f32
    const float* bcls = (const float*)d_in[5];  // () f32
    float* out = (float*)d_out;                 // (1,1,400,400) f32

    fused_dot_scatter_kernel<<<(NTHREADS + 255) / 256, 256>>>(td, cam, lc, mask, wcls);
    final_kernel<<<(NQ / 2 + 255) / 256, 256>>>(out, bcls);
}

// round 12
// speedup vs baseline: 1.0299x; 1.0133x over previous
#include <cuda_runtime.h>
#include <cstdint>

#define Hh 200
#define Ww 196
#define Cc 256
#define NCAMS 6
#define SSZ 400
#define NCELLS (SSZ*SSZ)
#define NPTS (Hh*Ww)     // 39200
#define HQ (Hh/4)        // 50
#define NSEG 4           // channel groups
#define CPG (Cc/NSEG)    // 64 channels per group
#define NTHREADS (NCAMS*Ww*NSEG*HQ)   // 235200 -> 919 CTAs of 256
#define NQ (NCELLS/4)
#define NPQ (Ww*HQ)                   // 9800 h-quads
#define NCPT (NCAMS*NPQ)              // 58800 cell tasks (one per cam x h-quad)
#define NBLK_CELL ((NCPT + 255) / 256)  // 230 producer blocks

// Zero-initialized at module load; final_kernel resets sum/cnt/g_done each
// launch so every launch / graph replay sees zeroed scratch. g_cell is fully
// rewritten by the prologue each launch (deterministic).
__device__ float    g_sum[NCELLS];
__device__ float    g_cnt[NCELLS];
__device__ int      g_cell[NCAMS * NPTS];  // [cam][w*Hh + h] = cell or -1
__device__ unsigned g_done;                // producer-block arrival counter

// Single hot kernel, <=36 regs (launch_bounds) -> 7 CTAs/SM -> 1064 capacity
// -> all 919 blocks in ONE wave (this was the R11 regression: 2 waves).
//  Prologue (blocks 0..229): projected cell table (mask+bounds folded in,
//    TRANSPOSED for coalesced int4 reads) + per-cell counts; arrive on g_done.
//  Body (all blocks): stream td_feats once (coalesced float4 over innermost
//    h), partial-dot 64 channels vs s_w.
//  Epilogue: wait g_done==230 (satisfied ~35us earlier), one coalesced int4
//    cell load, <=4 predicated sum atomics.
__global__ void __launch_bounds__(256, 7) fused_dot_scatter_kernel(
    const float* __restrict__ td, const float* __restrict__ cam,
    const float* __restrict__ lc, const void*  __restrict__ mask,
    const float* __restrict__ wcls)
{
    __shared__ float s_w[Cc];
    __shared__ int   s_mode;

    const bool cellblock = blockIdx.x < NBLK_CELL;

    // Mask-dtype fingerprint (mask ~90% true) over first 384 bytes:
    //   int32 0/1 : low byte of words sometimes set, upper 3 bytes never
    //   f32 0/1.0 : low byte never, upper bytes sometimes (0x3f800000)
    //   u8 bool   : both populated
    if (cellblock && threadIdx.x < 32) {
        const unsigned* mw = (const unsigned*)mask;
        unsigned lo = 0, hi = 0;
        #pragma unroll
        for (int k = 0; k < 3; ++k) {
            unsigned v = mw[threadIdx.x + 32 * k];
            lo |= (v & 0xFFu);
            hi |= (v & 0xFFFFFF00u);
        }
        unsigned any_lo = __ballot_sync(0xFFFFFFFF, lo != 0);
        unsigned any_hi = __ballot_sync(0xFFFFFFFF, hi != 0);
        if (threadIdx.x == 0) {
            int mode;
            if (any_lo && any_hi) mode = 1;   // u8 bool
            else if (any_lo)      mode = 0;   // int32
            else                  mode = 2;   // float32
            s_mode = mode;
        }
    }
    for (int i = threadIdx.x; i < Cc; i += blockDim.x) s_w[i] = wcls[i];
    __syncthreads();

    // ---- Prologue: cell table + counts (blocks 0..229) ----
    if (cellblock) {
        int ct = blockIdx.x * blockDim.x + threadIdx.x;
        if (ct < NCPT) {
            int mode = s_mode;
            int hq = ct % HQ;
            int t2 = ct / HQ;
            int w  = t2 % Ww;
            int c  = t2 / Ww;
            int h0 = hq * 4;

            const float* M = cam + c * 16;
            float m00 = __ldg(M + 0), m01 = __ldg(M + 1), m03 = __ldg(M + 3);
            float m10 = __ldg(M + 4), m11 = __ldg(M + 5), m13 = __ldg(M + 7);

            int4 cells;
            int* cl = (int*)&cells;
            #pragma unroll
            for (int k = 0; k < 4; ++k) {
                int n = (h0 + k) * Ww + w;       // ravel order of (H, W)
                float x = __ldg(lc + n);         // row 0 of logits_coordinates
                float y = __ldg(lc + NPTS + n);  // row 1
                bool mv;
                if (mode == 1)      mv = ((const unsigned char*)mask)[n] != 0;
                else if (mode == 0) mv = ((const int*)mask)[n] != 0;
                else                mv = ((const float*)mask)[n] != 0.f;

                float c0 = fmaf(m00, x, fmaf(m01, y, m03));
                float c1 = fmaf(m10, x, fmaf(m11, y, m13));
                // (coord+100)/0.5 == (coord+100)*2 exactly; jnp.round = half-even
                int i0 = (int)rintf((c0 + 100.0f) * 2.0f);
                int i1 = (int)rintf((c1 + 100.0f) * 2.0f);
                int cell = (mv && i0 >= 0 && i0 < SSZ && i1 >= 0 && i1 < SSZ)
                             ? (i0 * SSZ + i1) : -1;
                cl[k] = cell;
                if (cell >= 0) atomicAdd(&g_cnt[cell], 1.0f);  // counts: geometry only
            }
            *(int4*)(g_cell + c * NPTS + w * Hh + h0) = cells; // coalesced
        }
        __syncthreads();
        if (threadIdx.x == 0) {
            __threadfence();                     // publish table + counts
            atomicAdd(&g_done, 1u);
        }
    }

    // ---- Body: stream + partial dot ----
    int tid = blockIdx.x * blockDim.x + threadIdx.x;
    int hq = 0, w = 0, c = 0, h0 = 0;
    float acc0 = 0.f, acc1 = 0.f, acc2 = 0.f, acc3 = 0.f;
    const bool work = tid < NTHREADS;
    if (work) {
        // hq innermost for coalescing, then chan-group, then w, then cam
        hq  = tid % HQ;
        int t2 = tid / HQ;
        int seg = t2 % NSEG;
        int t3 = t2 / NSEG;
        w   = t3 % Ww;
        c   = t3 / Ww;
        h0  = hq * 4;
        int ch0 = seg * CPG;

        // td: ((c*C + ch)*W + w)*H + h ; h innermost, 16B aligned (H%4==0)
        const float4* __restrict__ base =
            (const float4*)(td + ((size_t)(c * Cc + ch0) * Ww + w) * Hh + h0);
        const int ch_stride4 = (Ww * Hh) / 4;   // 9800 float4 between channels

        #pragma unroll 8
        for (int ch = 0; ch < CPG; ++ch) {
            float4 v = __ldg(base + ch * ch_stride4);
            float wv = s_w[ch0 + ch];
            acc0 = fmaf(v.x, wv, acc0);
            acc1 = fmaf(v.y, wv, acc1);
            acc2 = fmaf(v.z, wv, acc2);
            acc3 = fmaf(v.w, wv, acc3);
        }
    }

    // ---- Wait for the cell table (satisfied long ago in steady state) ----
    if (threadIdx.x == 0) {
        while (*((volatile unsigned*)&g_done) < NBLK_CELL) { }
    }
    __syncthreads();
    __threadfence();   // acquire: table + counts visible

    if (work) {
        int4 cells = __ldg((const int4*)(g_cell + c * NPTS + w * Hh + h0));
        float accs[4] = {acc0, acc1, acc2, acc3};
        int   cls[4]  = {cells.x, cells.y, cells.z, cells.w};
        #pragma unroll
        for (int k = 0; k < 4; ++k) {
            if (cls[k] >= 0)
                atomicAdd(&g_sum[cls[k]], accs[k]);   // partial dot; linear so OK
        }
    }
}

// Consumes the accumulators AND resets all scratch (sum, cnt, g_done).
// float2 per thread -> 313 blocks (faster launch ramp than 157/79 blocks).
__global__ void __launch_bounds__(256) final_kernel(float* __restrict__ out,
                                                    const float* __restrict__ bcls) {
    int i = blockIdx.x * blockDim.x + threadIdx.x;
    if (i == 0) g_done = 0;
    if (i >= NCELLS / 2) return;
    float  b = __ldg(bcls);
    float2 s = ((const float2*)g_sum)[i];
    float2 n = ((const float2*)g_cnt)[i];
    float2 o;
    o.x = s.x / fmaxf(n.x, 1.0f) + b;   // cnt==0 -> sum==0 -> b (matches ref)
    o.y = s.y / fmaxf(n.y, 1.0f) + b;
    ((float2*)out)[i] = o;
    float2 z = make_float2(0.f, 0.f);
    ((float2*)g_sum)[i] = z;
    ((float2*)g_cnt)[i] = z;
}

extern "C" void kernel_launch(void* const* d_in, const int* in_sizes, int n_in,
                              void* d_out, int out_size) {
    const float* td   = (const float*)d_in[0];  // (1,6,256,196,200) f32
    const float* cam  = (const float*)d_in[1];  // (1,6,4,4) f32
    const float* lc   = (const float*)d_in[2];  // (4,39200) f32
    const void*  mask = (const void*) d_in[3];  // (200,196) bool-ish
    const float* wcls = (const float*)d_in[4];  // (256,) f32
    const float* bcls = (const float*)d_in[5];  // () f32
    float* out = (float*)d_out;                 // (1,1,400,400) f32

    fused_dot_scatter_kernel<<<(NTHREADS + 255) / 256, 256>>>(td, cam, lc, mask, wcls);
    final_kernel<<<(NCELLS / 2 + 255) / 256, 256>>>(out, bcls);
}

// round 14
// speedup vs baseline: 1.1031x; 1.0711x over previous
#include <cuda_runtime.h>
#include <cstdint>

#define Hh 200
#define Ww 196
#define Cc 256
#define NCAMS 6
#define SSZ 400
#define NCELLS (SSZ*SSZ)
#define NPTS (Hh*Ww)     // 39200
#define HQ (Hh/4)        // 50
#define NSEG 4           // channel groups
#define CPG (Cc/NSEG)    // 64 channels per group
#define NTHREADS (NCAMS*Ww*NSEG*HQ)     // 235200 -> 919 main blocks
#define NBLK_MAIN ((NTHREADS + 255) / 256)  // 919 (last block 64 threads idle)
#define NPQ (Ww*HQ)                     // 9800 h-quads
#define NCPT (NCAMS*NPQ)                // 58800 cell tasks
#define NBLK_CELL ((NCPT + 255) / 256)  // 230 producer blocks (FIRST in grid)
#define GRID (NBLK_CELL + NBLK_MAIN)    // 1149

// Zero-initialized at module load; final_kernel resets sum/cnt/g_done each
// launch so every launch / graph replay sees zeroed scratch. g_cell is fully
// rewritten by the producer blocks each launch (deterministic).
__device__ float    g_sum[NCELLS];
__device__ float    g_cnt[NCELLS];
__device__ int      g_cell[NCAMS * NPTS];  // [cam][w*Hh + h] = cell or -1
__device__ unsigned g_done;                // producer-block arrival counter

// One launch, two disjoint block roles:
//  Blocks 0..229 (producers, always wave-1): projected cell table (mask +
//    bounds folded in, TRANSPOSED for coalesced int4 reads) + per-cell
//    counts; arrive on g_done; exit (~5us).
//  Blocks 230..1148 (consumers): lean streaming body — 32 channels, then a
//    rendezvous on g_done (satisfied ~15us earlier) + int4 cell prefetch,
//    then 32 more channels hiding that load's latency, then <=4 predicated
//    sum atomics. NOTE: tail threads (tid >= NTHREADS) stay alive but
//    predicated ('work') because of the block-wide __syncthreads barriers.
__global__ void __launch_bounds__(256, 8) fused_dot_scatter_kernel(
    const float* __restrict__ td, const float* __restrict__ cam,
    const float* __restrict__ lc, const void*  __restrict__ mask,
    const float* __restrict__ wcls)
{
    if (blockIdx.x < NBLK_CELL) {
        // ---------------- Producer: cell table + counts ----------------
        __shared__ int s_mode;
        // Mask-dtype fingerprint (mask ~90% true) over first 384 bytes:
        //   int32 0/1 : low byte of words sometimes set, upper 3 bytes never
        //   f32 0/1.0 : low byte never, upper bytes sometimes (0x3f800000)
        //   u8 bool   : both populated
        if (threadIdx.x < 32) {
            const unsigned* mw = (const unsigned*)mask;
            unsigned lo = 0, hi = 0;
            #pragma unroll
            for (int k = 0; k < 3; ++k) {
                unsigned v = mw[threadIdx.x + 32 * k];
                lo |= (v & 0xFFu);
                hi |= (v & 0xFFFFFF00u);
            }
            unsigned any_lo = __ballot_sync(0xFFFFFFFF, lo != 0);
            unsigned any_hi = __ballot_sync(0xFFFFFFFF, hi != 0);
            if (threadIdx.x == 0) {
                int mode;
                if (any_lo && any_hi) mode = 1;   // u8 bool
                else if (any_lo)      mode = 0;   // int32
                else                  mode = 2;   // float32
                s_mode = mode;
            }
        }
        __syncthreads();

        int ct = blockIdx.x * blockDim.x + threadIdx.x;
        if (ct < NCPT) {
            int mode = s_mode;
            int hq = ct % HQ;
            int t2 = ct / HQ;
            int w  = t2 % Ww;
            int c  = t2 / Ww;
            int h0 = hq * 4;

            const float* M = cam + c * 16;
            float m00 = __ldg(M + 0), m01 = __ldg(M + 1), m03 = __ldg(M + 3);
            float m10 = __ldg(M + 4), m11 = __ldg(M + 5), m13 = __ldg(M + 7);

            int4 cells;
            int* cl = (int*)&cells;
            #pragma unroll
            for (int k = 0; k < 4; ++k) {
                int n = (h0 + k) * Ww + w;       // ravel order of (H, W)
                float x = __ldg(lc + n);         // row 0 of logits_coordinates
                float y = __ldg(lc + NPTS + n);  // row 1
                bool mv;
                if (mode == 1)      mv = ((const unsigned char*)mask)[n] != 0;
                else if (mode == 0) mv = ((const int*)mask)[n] != 0;
                else                mv = ((const float*)mask)[n] != 0.f;

                float c0 = fmaf(m00, x, fmaf(m01, y, m03));
                float c1 = fmaf(m10, x, fmaf(m11, y, m13));
                // (coord+100)/0.5 == (coord+100)*2 exactly; jnp.round = half-even
                int i0 = (int)rintf((c0 + 100.0f) * 2.0f);
                int i1 = (int)rintf((c1 + 100.0f) * 2.0f);
                int cell = (mv && i0 >= 0 && i0 < SSZ && i1 >= 0 && i1 < SSZ)
                             ? (i0 * SSZ + i1) : -1;
                cl[k] = cell;
                if (cell >= 0) atomicAdd(&g_cnt[cell], 1.0f);  // counts: geometry only
            }
            *(int4*)(g_cell + c * NPTS + w * Hh + h0) = cells; // coalesced
        }
        __syncthreads();
        if (threadIdx.x == 0) {
            __threadfence();                 // publish table + counts
            atomicAdd(&g_done, 1u);
        }
        return;
    }

    // ---------------- Consumer: lean stream + scatter ----------------
    __shared__ float s_w[Cc];
    for (int i = threadIdx.x; i < Cc; i += blockDim.x) s_w[i] = wcls[i];
    __syncthreads();

    int tid = (blockIdx.x - NBLK_CELL) * blockDim.x + threadIdx.x;
    const bool work = tid < NTHREADS;     // tail of last block: stay for barriers
    int t = work ? tid : 0;               // safe dummy indices for idle threads
    // hq innermost for coalescing, then chan-group, then w, then cam
    int hq  = t % HQ;
    int t2  = t / HQ;
    int seg = t2 % NSEG;
    int t3  = t2 / NSEG;
    int w   = t3 % Ww;
    int c   = t3 / Ww;
    int h0  = hq * 4;
    int ch0 = seg * CPG;

    // td flat index: ((c*C + ch)*W + w)*H + h ; h innermost, 16B aligned (H%4==0)
    const float4* __restrict__ base =
        (const float4*)(td + ((size_t)(c * Cc + ch0) * Ww + w) * Hh + h0);
    const int ch_stride4 = (Ww * Hh) / 4;   // 9800 float4 between channels

    float acc0 = 0.f, acc1 = 0.f, acc2 = 0.f, acc3 = 0.f;

    // First half of the channel stream.
    if (work) {
        #pragma unroll 8
        for (int ch = 0; ch < CPG / 2; ++ch) {
            float4 v = __ldg(base + ch * ch_stride4);
            float wv = s_w[ch0 + ch];
            acc0 = fmaf(v.x, wv, acc0);
            acc1 = fmaf(v.y, wv, acc1);
            acc2 = fmaf(v.z, wv, acc2);
            acc3 = fmaf(v.w, wv, acc3);
        }
    }

    // Rendezvous: producers finished ~15us ago in steady state.
    if (threadIdx.x == 0) {
        while (*((volatile unsigned*)&g_done) < NBLK_CELL) { __nanosleep(64); }
    }
    __syncthreads();
    __threadfence();   // acquire: table + counts visible

    // Prefetch the cell vector; its latency hides under the second half.
    int4 cells = make_int4(-1, -1, -1, -1);
    if (work) {
        cells = __ldg((const int4*)(g_cell + c * NPTS + w * Hh + h0));
        #pragma unroll 8
        for (int ch = CPG / 2; ch < CPG; ++ch) {
            float4 v = __ldg(base + ch * ch_stride4);
            float wv = s_w[ch0 + ch];
            acc0 = fmaf(v.x, wv, acc0);
            acc1 = fmaf(v.y, wv, acc1);
            acc2 = fmaf(v.z, wv, acc2);
            acc3 = fmaf(v.w, wv, acc3);
        }

        float accs[4] = {acc0, acc1, acc2, acc3};
        int   cls[4]  = {cells.x, cells.y, cells.z, cells.w};
        #pragma unroll
        for (int k = 0; k < 4; ++k) {
            if (cls[k] >= 0)
                atomicAdd(&g_sum[cls[k]], accs[k]);   // partial dot; linear so OK
        }
    }
}

// Consumes the accumulators AND resets all scratch (sum, cnt, g_done).
__global__ void __launch_bounds__(256) final_kernel(float* __restrict__ out,
                                                    const float* __restrict__ bcls) {
    int i = blockIdx.x * blockDim.x + threadIdx.x;
    if (i == 0) g_done = 0;
    if (i >= NCELLS / 2) return;
    float  b = __ldg(bcls);
    float2 s = ((const float2*)g_sum)[i];
    float2 n = ((const float2*)g_cnt)[i];
    float2 o;
    o.x = s.x / fmaxf(n.x, 1.0f) + b;   // cnt==0 -> sum==0 -> b (matches ref)
    o.y = s.y / fmaxf(n.y, 1.0f) + b;
    ((float2*)out)[i] = o;
    float2 z = make_float2(0.f, 0.f);
    ((float2*)g_sum)[i] = z;
    ((float2*)g_cnt)[i] = z;
}

extern "C" void kernel_launch(void* const* d_in, const int* in_sizes, int n_in,
                              void* d_out, int out_size) {
    const float* td   = (const float*)d_in[0];  // (1,6,256,196,200) f32
    const float* cam  = (const float*)d_in[1];  // (1,6,4,4) f32
    const float* lc   = (const float*)d_in[2];  // (4,39200) f32
    const void*  mask = (const void*) d_in[3];  // (200,196) bool-ish
    const float* wcls = (const float*)d_in[4];  // (256,) f32
    const float* bcls = (const float*)d_in[5];  // () f32
    float* out = (float*)d_out;                 // (1,1,400,400) f32

    fused_dot_scatter_kernel<<<GRID, 256>>>(td, cam, lc, mask, wcls);
    final_kernel<<<(NCELLS / 2 + 255) / 256, 256>>>(out, bcls);
}